// round 6
// baseline (speedup 1.0000x reference)
#include <cuda_runtime.h>
#include <cuda_bf16.h>
#include <math.h>
#include <cstdint>

#define TT 128
#define BB 256
#define DIN 512
#define H1 1024
#define H2 1024
#define H3 512

typedef __nv_bfloat16 bf16;

// ---------------- persistent device storage ---------------------------------
__device__ bf16 g_x_hi[TT * BB * DIN];
__device__ bf16 g_x_lo[TT * BB * DIN];
__device__ float g_xpre[(size_t)TT * BB * 4 * H1];   // precomputed x@Wih1^T

__device__ bf16 g_W1h_hi[4 * H1 * H1],  g_W1h_lo[4 * H1 * H1];
__device__ bf16 g_W1i_hi[4 * H1 * DIN], g_W1i_lo[4 * H1 * DIN];
__device__ bf16 g_W2i_hi[4 * H2 * H1],  g_W2i_lo[4 * H2 * H1];
__device__ bf16 g_W2h_hi[4 * H2 * H2],  g_W2h_lo[4 * H2 * H2];
__device__ bf16 g_W3i_hi[4 * H3 * H2],  g_W3i_lo[4 * H3 * H2];
__device__ bf16 g_W3h_hi[4 * H3 * H3],  g_W3h_lo[4 * H3 * H3];

__device__ bf16 g_h1_hi[2][BB * H1], g_h1_lo[2][BB * H1];
__device__ bf16 g_h2_hi[2][BB * H2], g_h2_lo[2][BB * H2];
__device__ bf16 g_h3_hi[2][BB * H3], g_h3_lo[2][BB * H3];

__device__ float g_c1[BB * H1], g_c2[BB * H2], g_c3[BB * H3];
__device__ float g_hf1[BB * H1], g_hf2[BB * H2], g_hf3[BB * H3];

// ---------------- helpers ----------------------------------------------------
__device__ __forceinline__ uint32_t smem_u32(const void* p) {
    uint32_t a;
    asm("{ .reg .u64 t; cvta.to.shared.u64 t, %1; cvt.u32.u64 %0, t; }" : "=r"(a) : "l"(p));
    return a;
}
__device__ __forceinline__ void cp16(uint32_t smem, const void* gmem) {
    asm volatile("cp.async.cg.shared.global [%0], [%1], 16;\n" ::"r"(smem), "l"(gmem));
}
#define CP_COMMIT() asm volatile("cp.async.commit_group;\n" ::: "memory")
#define CP_WAIT(n)  asm volatile("cp.async.wait_group %0;\n" ::"n"(n) : "memory")

__device__ __forceinline__ void ldsm4(unsigned* d, uint32_t addr) {
    asm volatile("ldmatrix.sync.aligned.m8n8.x4.shared.b16 {%0,%1,%2,%3}, [%4];"
                 : "=r"(d[0]), "=r"(d[1]), "=r"(d[2]), "=r"(d[3]) : "r"(addr));
}
__device__ __forceinline__ void mma_bf16(float* c, const unsigned* a, unsigned b0, unsigned b1) {
    asm volatile(
        "mma.sync.aligned.m16n8k16.row.col.f32.bf16.bf16.f32 "
        "{%0,%1,%2,%3},{%4,%5,%6,%7},{%8,%9},{%0,%1,%2,%3};\n"
        : "+f"(c[0]), "+f"(c[1]), "+f"(c[2]), "+f"(c[3])
        : "r"(a[0]), "r"(a[1]), "r"(a[2]), "r"(a[3]), "r"(b0), "r"(b1));
}
__device__ __forceinline__ float sigm(float x) { return 1.0f / (1.0f + __expf(-x)); }

// ---------------------------------------------------------------------------
// Tiled 3-term bf16-split GEMM, tile 128(batch) x 128(32 j x 4 gates).
// 8 warps = 2(m-half) x 4(j-slice of 8). Each warp computes ALL 4 gates for
// its j-slice (gate = fragment index), so a thread holds i/f/g/o for its
// (b, j-pair) in registers -> in-register LSTM epilogue, no smem staging.
// 3-stage cp.async pipeline, 1 syncthreads per K=64 chunk.
// ---------------------------------------------------------------------------
#define BM 128
#define PITCH 72
#define A_STG (BM * PITCH)
#define B_STG (128 * PITCH)
#define STG_ELEMS (A_STG + B_STG)
#define DYN_BYTES (3 * STG_ELEMS * 2)   // 110592 bytes

template <int K1, int K2, int HH, bool PRE>
__global__ __launch_bounds__(256, 2)
void gemm_kernel(const bf16* __restrict__ Ai_hi, const bf16* __restrict__ Ai_lo,
                 const bf16* __restrict__ Ah_hi, const bf16* __restrict__ Ah_lo,
                 const bf16* __restrict__ Wi_hi, const bf16* __restrict__ Wi_lo,
                 const bf16* __restrict__ Wh_hi, const bf16* __restrict__ Wh_lo,
                 const float* __restrict__ bih, const float* __restrict__ bhh,
                 const float* __restrict__ xpre,
                 float* __restrict__ c, float* __restrict__ hf,
                 bf16* __restrict__ ho_hi, bf16* __restrict__ ho_lo,
                 float* __restrict__ gout)
{
    constexpr int KK = K1 + K2;
    constexpr int NCH = 3 * KK / 64;

    extern __shared__ __align__(16) bf16 dyn[];
    const uint32_t sbase = smem_u32(dyn);

    const int tid = threadIdx.x;
    const int wid = tid >> 5, lane = tid & 31;
    const int wm = wid >> 2, wn = wid & 3;     // m-half (64 rows), j-slice (8)
    const int j0 = blockIdx.x * 32;
    const int b0 = blockIdx.y * BM;

    float acc[4][4][4];   // [mi][gate][frag]
#pragma unroll
    for (int mi = 0; mi < 4; ++mi)
#pragma unroll
        for (int g = 0; g < 4; ++g)
#pragma unroll
            for (int r = 0; r < 4; ++r) acc[mi][g][r] = 0.0f;

    auto load_stage = [&](int ci, int s) {
        const int kg = ci * 64;
        const int term = kg / KK;
        const int kk = kg - term * KK;
        const bf16 *A, *W;
        int col, ld;
        if (kk < K1) {
            A = (term == 1) ? Ai_lo : Ai_hi;
            W = (term == 2) ? Wi_lo : Wi_hi;
            col = kk; ld = K1;
        } else {
            A = (term == 1) ? Ah_lo : Ah_hi;
            W = (term == 2) ? Wh_lo : Wh_hi;
            col = kk - K1; ld = K2;
        }
        const uint32_t abase = sbase + (uint32_t)(s * STG_ELEMS) * 2;
        const uint32_t bbase = abase + A_STG * 2;
#pragma unroll
        for (int it = 0; it < 4; ++it) {           // A: 128 rows x 8 quads
            const int idx = tid + it * 256;
            const int r = idx >> 3, q = idx & 7;
            cp16(abase + (uint32_t)(r * PITCH + q * 8) * 2,
                 A + (size_t)(b0 + r) * ld + col + q * 8);
        }
#pragma unroll
        for (int it = 0; it < 4; ++it) {           // B: 128 rows (gate*32+jl)
            const int idx = tid + it * 256;
            const int r = idx >> 3, q = idx & 7;
            const int gate = r >> 5, jl = r & 31;
            cp16(bbase + (uint32_t)(r * PITCH + q * 8) * 2,
                 W + (size_t)(gate * HH + j0 + jl) * ld + col + q * 8);
        }
        CP_COMMIT();
    };

    const int arow_off = lane & 15, acol_off = (lane >> 4) << 3;
    const int b_gsel = (lane >> 3) & 1;            // gate parity within pair
    const int b_kadd = (lane >> 4) << 3;
    const int b_jrow = wn * 8 + (lane & 7);

    auto compute = [&](int s) {
        const uint32_t abase = sbase + (uint32_t)(s * STG_ELEMS) * 2;
        const uint32_t bbase = abase + A_STG * 2;
#pragma unroll
        for (int kh = 0; kh < 4; ++kh) {
            const int kc = kh * 16;
            unsigned a[4][4], bA[4], bB[4];
            // bA: gates 0,1 ; bB: gates 2,3 (per-lane gathered rows)
            ldsm4(bA, bbase + (uint32_t)((b_gsel * 32 + b_jrow) * PITCH + kc + b_kadd) * 2);
            ldsm4(bB, bbase + (uint32_t)(((2 + b_gsel) * 32 + b_jrow) * PITCH + kc + b_kadd) * 2);
#pragma unroll
            for (int mi = 0; mi < 4; ++mi) {
                const int row = wm * 64 + mi * 16 + arow_off;
                ldsm4(a[mi], abase + (uint32_t)(row * PITCH + kc + acol_off) * 2);
            }
#pragma unroll
            for (int mi = 0; mi < 4; ++mi) {
                mma_bf16(acc[mi][0], a[mi], bA[0], bA[2]);
                mma_bf16(acc[mi][1], a[mi], bA[1], bA[3]);
                mma_bf16(acc[mi][2], a[mi], bB[0], bB[2]);
                mma_bf16(acc[mi][3], a[mi], bB[1], bB[3]);
            }
        }
    };

    load_stage(0, 0);
    load_stage(1, 1);

    for (int ci = 0; ci < NCH; ++ci) {
        if (ci == NCH - 1) { CP_WAIT(0); } else { CP_WAIT(1); }
        __syncthreads();
        if (ci + 2 < NCH) load_stage(ci + 2, (ci + 2) % 3);
        compute(ci % 3);
    }

    // ---------------- in-register epilogue ----------------
    const int g4 = lane >> 2, tg = lane & 3;
    const int j = j0 + wn * 8 + tg * 2;            // this thread's j-pair

    if (PRE) {
#pragma unroll
        for (int mi = 0; mi < 4; ++mi)
#pragma unroll
            for (int rh = 0; rh < 2; ++rh) {
                const int b = b0 + wm * 64 + mi * 16 + g4 + rh * 8;
                float* orow = gout + (size_t)b * (4 * HH) + j;
#pragma unroll
                for (int g = 0; g < 4; ++g) {
                    float2 v = make_float2(acc[mi][g][rh * 2], acc[mi][g][rh * 2 + 1]);
                    *reinterpret_cast<float2*>(orow + g * HH) = v;
                }
            }
    } else {
        float2 bsum[4];
#pragma unroll
        for (int g = 0; g < 4; ++g) {
            const float2 bi = *reinterpret_cast<const float2*>(bih + g * HH + j);
            const float2 bh = *reinterpret_cast<const float2*>(bhh + g * HH + j);
            bsum[g] = make_float2(bi.x + bh.x, bi.y + bh.y);
        }
#pragma unroll
        for (int mi = 0; mi < 4; ++mi)
#pragma unroll
            for (int rh = 0; rh < 2; ++rh) {
                const int b = b0 + wm * 64 + mi * 16 + g4 + rh * 8;
                float2 gv[4];
#pragma unroll
                for (int g = 0; g < 4; ++g)
                    gv[g] = make_float2(acc[mi][g][rh * 2] + bsum[g].x,
                                        acc[mi][g][rh * 2 + 1] + bsum[g].y);
                if (xpre) {
                    const float* xr = xpre + (size_t)b * (4 * HH) + j;
#pragma unroll
                    for (int g = 0; g < 4; ++g) {
                        const float2 xv = *reinterpret_cast<const float2*>(xr + g * HH);
                        gv[g].x += xv.x; gv[g].y += xv.y;
                    }
                }
                const size_t off = (size_t)b * HH + j;
                const float2 cv = *reinterpret_cast<const float2*>(c + off);

                const float i0 = sigm(gv[0].x), i1 = sigm(gv[0].y);
                const float f0 = sigm(gv[1].x), f1 = sigm(gv[1].y);
                const float g0 = tanhf(gv[2].x), g1 = tanhf(gv[2].y);
                const float o0 = sigm(gv[3].x), o1 = sigm(gv[3].y);
                const float cn0 = f0 * cv.x + i0 * g0;
                const float cn1 = f1 * cv.y + i1 * g1;
                *reinterpret_cast<float2*>(c + off) = make_float2(cn0, cn1);
                const float hn0 = o0 * tanhf(cn0);
                const float hn1 = o1 * tanhf(cn1);
                *reinterpret_cast<float2*>(hf + off) = make_float2(hn0, hn1);
                const bf16 h0 = __float2bfloat16(hn0);
                const bf16 h1 = __float2bfloat16(hn1);
                __nv_bfloat162 hi2 = __nv_bfloat162(h0, h1);
                __nv_bfloat162 lo2 = __nv_bfloat162(
                    __float2bfloat16(hn0 - __bfloat162float(h0)),
                    __float2bfloat16(hn1 - __bfloat162float(h1)));
                *reinterpret_cast<__nv_bfloat162*>(ho_hi + off) = hi2;
                *reinterpret_cast<__nv_bfloat162*>(ho_lo + off) = lo2;
            }
    }
}

// ---------------- prep / init / finalize ------------------------------------
__global__ void split_kernel(const float* __restrict__ src, bf16* __restrict__ hi,
                             bf16* __restrict__ lo, int n) {
    int i = blockIdx.x * blockDim.x + threadIdx.x;
    const int st = gridDim.x * blockDim.x;
    for (; i < n; i += st) {
        const float v = src[i];
        const bf16 h = __float2bfloat16(v);
        hi[i] = h;
        lo[i] = __float2bfloat16(v - __bfloat162float(h));
    }
}

__global__ void init_state_kernel() {
    int idx = blockIdx.x * blockDim.x + threadIdx.x;
    const int st = gridDim.x * blockDim.x;
    const int N1 = BB * H1, N3 = BB * H3;
    const bf16 z = __float2bfloat16(0.0f);
    for (int i = idx; i < N1; i += st) {
        g_h1_hi[0][i] = z; g_h1_lo[0][i] = z; g_h1_hi[1][i] = z; g_h1_lo[1][i] = z;
        g_h2_hi[0][i] = z; g_h2_lo[0][i] = z; g_h2_hi[1][i] = z; g_h2_lo[1][i] = z;
        g_c1[i] = 0.f; g_c2[i] = 0.f;
    }
    for (int i = idx; i < N3; i += st) {
        g_h3_hi[0][i] = z; g_h3_lo[0][i] = z; g_h3_hi[1][i] = z; g_h3_lo[1][i] = z;
        g_c3[i] = 0.f;
    }
}

__global__ void finalize_kernel(float* __restrict__ out) {
    int idx = blockIdx.x * blockDim.x + threadIdx.x;
    const int st = gridDim.x * blockDim.x;
    const int N1 = BB * H1, N3 = BB * H3;
    for (int i = idx; i < N1; i += st) {
        out[0 * N1 + i] = g_hf1[i];
        out[1 * N1 + i] = g_c1[i];
        out[2 * N1 + i] = g_hf2[i];
        out[3 * N1 + i] = g_c2[i];
    }
    for (int i = idx; i < N3; i += st) {
        out[4 * N1 + i] = g_hf3[i];
        out[4 * N1 + N3 + i] = g_c3[i];
    }
}

// ---------------- launch ----------------------------------------------------
extern "C" void kernel_launch(void* const* d_in, const int* in_sizes, int n_in,
                              void* d_out, int out_size) {
    const float* x    = (const float*)d_in[0];
    const float* Wih1 = (const float*)d_in[1];
    const float* Whh1 = (const float*)d_in[2];
    const float* bih1 = (const float*)d_in[3];
    const float* bhh1 = (const float*)d_in[4];
    const float* Wih2 = (const float*)d_in[5];
    const float* Whh2 = (const float*)d_in[6];
    const float* bih2 = (const float*)d_in[7];
    const float* bhh2 = (const float*)d_in[8];
    const float* Wih3 = (const float*)d_in[9];
    const float* Whh3 = (const float*)d_in[10];
    const float* bih3 = (const float*)d_in[11];
    const float* bhh3 = (const float*)d_in[12];
    float* out = (float*)d_out;

    bf16 *x_hi, *x_lo;
    bf16 *W1i_hi, *W1i_lo, *W1h_hi, *W1h_lo;
    bf16 *W2i_hi, *W2i_lo, *W2h_hi, *W2h_lo;
    bf16 *W3i_hi, *W3i_lo, *W3h_hi, *W3h_lo;
    bf16 *h1_hi, *h1_lo, *h2_hi, *h2_lo, *h3_hi, *h3_lo;
    float *c1, *c2, *c3, *hf1, *hf2, *hf3, *xpre;

    cudaGetSymbolAddress((void**)&x_hi, g_x_hi);
    cudaGetSymbolAddress((void**)&x_lo, g_x_lo);
    cudaGetSymbolAddress((void**)&xpre, g_xpre);
    cudaGetSymbolAddress((void**)&W1i_hi, g_W1i_hi);
    cudaGetSymbolAddress((void**)&W1i_lo, g_W1i_lo);
    cudaGetSymbolAddress((void**)&W1h_hi, g_W1h_hi);
    cudaGetSymbolAddress((void**)&W1h_lo, g_W1h_lo);
    cudaGetSymbolAddress((void**)&W2i_hi, g_W2i_hi);
    cudaGetSymbolAddress((void**)&W2i_lo, g_W2i_lo);
    cudaGetSymbolAddress((void**)&W2h_hi, g_W2h_hi);
    cudaGetSymbolAddress((void**)&W2h_lo, g_W2h_lo);
    cudaGetSymbolAddress((void**)&W3i_hi, g_W3i_hi);
    cudaGetSymbolAddress((void**)&W3i_lo, g_W3i_lo);
    cudaGetSymbolAddress((void**)&W3h_hi, g_W3h_hi);
    cudaGetSymbolAddress((void**)&W3h_lo, g_W3h_lo);
    cudaGetSymbolAddress((void**)&h1_hi, g_h1_hi);
    cudaGetSymbolAddress((void**)&h1_lo, g_h1_lo);
    cudaGetSymbolAddress((void**)&h2_hi, g_h2_hi);
    cudaGetSymbolAddress((void**)&h2_lo, g_h2_lo);
    cudaGetSymbolAddress((void**)&h3_hi, g_h3_hi);
    cudaGetSymbolAddress((void**)&h3_lo, g_h3_lo);
    cudaGetSymbolAddress((void**)&c1, g_c1);
    cudaGetSymbolAddress((void**)&c2, g_c2);
    cudaGetSymbolAddress((void**)&c3, g_c3);
    cudaGetSymbolAddress((void**)&hf1, g_hf1);
    cudaGetSymbolAddress((void**)&hf2, g_hf2);
    cudaGetSymbolAddress((void**)&hf3, g_hf3);

    cudaFuncSetAttribute(gemm_kernel<DIN, 0, H1, true>,
                         cudaFuncAttributeMaxDynamicSharedMemorySize, DYN_BYTES);
    cudaFuncSetAttribute(gemm_kernel<H1, 0, H1, false>,
                         cudaFuncAttributeMaxDynamicSharedMemorySize, DYN_BYTES);
    cudaFuncSetAttribute(gemm_kernel<H1, H2, H2, false>,
                         cudaFuncAttributeMaxDynamicSharedMemorySize, DYN_BYTES);
    cudaFuncSetAttribute(gemm_kernel<H2, H3, H3, false>,
                         cudaFuncAttributeMaxDynamicSharedMemorySize, DYN_BYTES);

    static cudaStream_t s1 = nullptr, s2 = nullptr, s3 = nullptr;
    static cudaEvent_t ev1r[4], ev2r[4], ev3r[4], evFork, evJ1, evJ2, evJ3;
    if (!s1) {
        cudaStreamCreateWithFlags(&s1, cudaStreamNonBlocking);
        cudaStreamCreateWithFlags(&s2, cudaStreamNonBlocking);
        cudaStreamCreateWithFlags(&s3, cudaStreamNonBlocking);
        for (int i = 0; i < 4; ++i) {
            cudaEventCreateWithFlags(&ev1r[i], cudaEventDisableTiming);
            cudaEventCreateWithFlags(&ev2r[i], cudaEventDisableTiming);
            cudaEventCreateWithFlags(&ev3r[i], cudaEventDisableTiming);
        }
        cudaEventCreateWithFlags(&evFork, cudaEventDisableTiming);
        cudaEventCreateWithFlags(&evJ1, cudaEventDisableTiming);
        cudaEventCreateWithFlags(&evJ2, cudaEventDisableTiming);
        cudaEventCreateWithFlags(&evJ3, cudaEventDisableTiming);
    }

    // -------- prologue (legacy stream) --------
    split_kernel<<<2048, 256>>>(x, x_hi, x_lo, TT * BB * DIN);
    split_kernel<<<1024, 256>>>(Wih1, W1i_hi, W1i_lo, 4 * H1 * DIN);
    split_kernel<<<1024, 256>>>(Whh1, W1h_hi, W1h_lo, 4 * H1 * H1);
    split_kernel<<<1024, 256>>>(Wih2, W2i_hi, W2i_lo, 4 * H2 * H1);
    split_kernel<<<1024, 256>>>(Whh2, W2h_hi, W2h_lo, 4 * H2 * H2);
    split_kernel<<<1024, 256>>>(Wih3, W3i_hi, W3i_lo, 4 * H3 * H2);
    split_kernel<<<1024, 256>>>(Whh3, W3h_hi, W3h_lo, 4 * H3 * H3);
    init_state_kernel<<<512, 256>>>();

    // big precompute: X1 = x @ Wih1^T for all T*B rows
    gemm_kernel<DIN, 0, H1, true><<<dim3(H1 / 32, TT * BB / BM), 256, DYN_BYTES>>>(
        x_hi, x_lo, nullptr, nullptr, W1i_hi, W1i_lo, nullptr, nullptr,
        nullptr, nullptr, nullptr, nullptr, nullptr, nullptr, nullptr, xpre);

    cudaEventRecord(evFork, 0);
    cudaStreamWaitEvent(s1, evFork, 0);
    cudaStreamWaitEvent(s2, evFork, 0);
    cudaStreamWaitEvent(s3, evFork, 0);

    const int N1 = BB * H1, N2 = BB * H2, N3 = BB * H3;

    for (int t = 0; t < TT; ++t) {
        const int pi = t & 1, po = (t + 1) & 1;

        if (t >= 2) cudaStreamWaitEvent(s1, ev2r[(t - 2) & 3], 0);
        gemm_kernel<H1, 0, H1, false><<<dim3(H1 / 32, BB / BM), 256, DYN_BYTES, s1>>>(
            h1_hi + pi * N1, h1_lo + pi * N1, nullptr, nullptr,
            W1h_hi, W1h_lo, nullptr, nullptr,
            bih1, bhh1, xpre + (size_t)t * BB * 4 * H1,
            c1, hf1, h1_hi + po * N1, h1_lo + po * N1, nullptr);
        cudaEventRecord(ev1r[t & 3], s1);

        cudaStreamWaitEvent(s2, ev1r[t & 3], 0);
        if (t >= 2) cudaStreamWaitEvent(s2, ev3r[(t - 2) & 3], 0);
        gemm_kernel<H1, H2, H2, false><<<dim3(H2 / 32, BB / BM), 256, DYN_BYTES, s2>>>(
            h1_hi + po * N1, h1_lo + po * N1, h2_hi + pi * N2, h2_lo + pi * N2,
            W2i_hi, W2i_lo, W2h_hi, W2h_lo,
            bih2, bhh2, nullptr,
            c2, hf2, h2_hi + po * N2, h2_lo + po * N2, nullptr);
        cudaEventRecord(ev2r[t & 3], s2);

        cudaStreamWaitEvent(s3, ev2r[t & 3], 0);
        gemm_kernel<H2, H3, H3, false><<<dim3(H3 / 32, BB / BM), 256, DYN_BYTES, s3>>>(
            h2_hi + po * N2, h2_lo + po * N2, h3_hi + pi * N3, h3_lo + pi * N3,
            W3i_hi, W3i_lo, W3h_hi, W3h_lo,
            bih3, bhh3, nullptr,
            c3, hf3, h3_hi + po * N3, h3_lo + po * N3, nullptr);
        cudaEventRecord(ev3r[t & 3], s3);
    }

    cudaEventRecord(evJ1, s1);
    cudaEventRecord(evJ2, s2);
    cudaEventRecord(evJ3, s3);
    cudaStreamWaitEvent(0, evJ1, 0);
    cudaStreamWaitEvent(0, evJ2, 0);
    cudaStreamWaitEvent(0, evJ3, 0);

    finalize_kernel<<<256, 256>>>(out);
}

// round 7
// speedup vs baseline: 1.2594x; 1.2594x over previous
#include <cuda_runtime.h>
#include <cuda_bf16.h>
#include <math.h>
#include <cstdint>

#define TT 128
#define BB 256
#define DIN 512
#define H1 1024
#define H2 1024
#define H3 512

typedef __nv_bfloat16 bf16;

// ---------------- persistent device storage ---------------------------------
__device__ bf16 g_x_hi[TT * BB * DIN];
__device__ bf16 g_x_lo[TT * BB * DIN];
__device__ float g_xpre[(size_t)TT * BB * 4 * H1];   // precomputed x@Wih1^T

__device__ bf16 g_W1h_hi[4 * H1 * H1],  g_W1h_lo[4 * H1 * H1];
__device__ bf16 g_W1i_hi[4 * H1 * DIN], g_W1i_lo[4 * H1 * DIN];
__device__ bf16 g_W2i_hi[4 * H2 * H1],  g_W2i_lo[4 * H2 * H1];
__device__ bf16 g_W2h_hi[4 * H2 * H2],  g_W2h_lo[4 * H2 * H2];
__device__ bf16 g_W3i_hi[4 * H3 * H2],  g_W3i_lo[4 * H3 * H2];
__device__ bf16 g_W3h_hi[4 * H3 * H3],  g_W3h_lo[4 * H3 * H3];

__device__ bf16 g_h1_hi[2][BB * H1], g_h1_lo[2][BB * H1];
__device__ bf16 g_h2_hi[2][BB * H2], g_h2_lo[2][BB * H2];
__device__ bf16 g_h3_hi[2][BB * H3], g_h3_lo[2][BB * H3];

__device__ float g_c1[BB * H1], g_c2[BB * H2], g_c3[BB * H3];

// ---------------- helpers ----------------------------------------------------
__device__ __forceinline__ uint32_t smem_u32(const void* p) {
    uint32_t a;
    asm("{ .reg .u64 t; cvta.to.shared.u64 t, %1; cvt.u32.u64 %0, t; }" : "=r"(a) : "l"(p));
    return a;
}
__device__ __forceinline__ void cp16(uint32_t smem, const void* gmem) {
    asm volatile("cp.async.cg.shared.global [%0], [%1], 16;\n" ::"r"(smem), "l"(gmem));
}
#define CP_COMMIT() asm volatile("cp.async.commit_group;\n" ::: "memory")
#define CP_WAIT(n)  asm volatile("cp.async.wait_group %0;\n" ::"n"(n) : "memory")

__device__ __forceinline__ void ldsm4(unsigned* d, uint32_t addr) {
    asm volatile("ldmatrix.sync.aligned.m8n8.x4.shared.b16 {%0,%1,%2,%3}, [%4];"
                 : "=r"(d[0]), "=r"(d[1]), "=r"(d[2]), "=r"(d[3]) : "r"(addr));
}
__device__ __forceinline__ void mma_bf16(float* c, const unsigned* a, unsigned b0, unsigned b1) {
    asm volatile(
        "mma.sync.aligned.m16n8k16.row.col.f32.bf16.bf16.f32 "
        "{%0,%1,%2,%3},{%4,%5,%6,%7},{%8,%9},{%0,%1,%2,%3};\n"
        : "+f"(c[0]), "+f"(c[1]), "+f"(c[2]), "+f"(c[3])
        : "r"(a[0]), "r"(a[1]), "r"(a[2]), "r"(a[3]), "r"(b0), "r"(b1));
}
__device__ __forceinline__ float sigm(float x) { return 1.0f / (1.0f + __expf(-x)); }

// ---------------------------------------------------------------------------
// Tiled 3-term bf16-split GEMM, tile 64(batch) x 128(32 j x 4 gates).
// 8 warps = 2(m:32 rows) x 4(j-slice of 8). Each warp computes ALL 4 gates
// for its j-slice -> in-register LSTM epilogue, no smem staging.
// Grid (H/32, BB/64) = 128 CTAs for H=1024 -> full chip fill.
// 4-stage cp.async pipeline, 1 syncthreads per K=64 chunk.
// ---------------------------------------------------------------------------
#define BM 64
#define PITCH 72
#define A_STG (BM * PITCH)
#define B_STG (128 * PITCH)
#define STG_ELEMS (A_STG + B_STG)
#define DYN_BYTES (4 * STG_ELEMS * 2)   // 110592 bytes

template <int K1, int K2, int HH, bool PRE>
__global__ __launch_bounds__(256, 2)
void gemm_kernel(const bf16* __restrict__ Ai_hi, const bf16* __restrict__ Ai_lo,
                 const bf16* __restrict__ Ah_hi, const bf16* __restrict__ Ah_lo,
                 const bf16* __restrict__ Wi_hi, const bf16* __restrict__ Wi_lo,
                 const bf16* __restrict__ Wh_hi, const bf16* __restrict__ Wh_lo,
                 const float* __restrict__ bih, const float* __restrict__ bhh,
                 const float* __restrict__ xpre,
                 float* __restrict__ c,
                 bf16* __restrict__ ho_hi, bf16* __restrict__ ho_lo,
                 float* __restrict__ gout)
{
    constexpr int KK = K1 + K2;
    constexpr int NCH = 3 * KK / 64;

    extern __shared__ __align__(16) bf16 dyn[];
    const uint32_t sbase = smem_u32(dyn);

    const int tid = threadIdx.x;
    const int wid = tid >> 5, lane = tid & 31;
    const int wm = wid >> 2, wn = wid & 3;     // m-half (32 rows), j-slice (8)
    const int j0 = blockIdx.x * 32;
    const int b0 = blockIdx.y * BM;

    float acc[2][4][4];   // [mi][gate][frag]
#pragma unroll
    for (int mi = 0; mi < 2; ++mi)
#pragma unroll
        for (int g = 0; g < 4; ++g)
#pragma unroll
            for (int r = 0; r < 4; ++r) acc[mi][g][r] = 0.0f;

    auto load_stage = [&](int ci, int s) {
        const int kg = ci * 64;
        const int term = kg / KK;
        const int kk = kg - term * KK;
        const bf16 *A, *W;
        int col, ld;
        if (kk < K1) {
            A = (term == 1) ? Ai_lo : Ai_hi;
            W = (term == 2) ? Wi_lo : Wi_hi;
            col = kk; ld = K1;
        } else {
            A = (term == 1) ? Ah_lo : Ah_hi;
            W = (term == 2) ? Wh_lo : Wh_hi;
            col = kk - K1; ld = K2;
        }
        const uint32_t abase = sbase + (uint32_t)(s * STG_ELEMS) * 2;
        const uint32_t bbase = abase + A_STG * 2;
#pragma unroll
        for (int it = 0; it < 2; ++it) {           // A: 64 rows x 8 quads
            const int idx = tid + it * 256;
            const int r = idx >> 3, q = idx & 7;
            cp16(abase + (uint32_t)(r * PITCH + q * 8) * 2,
                 A + (size_t)(b0 + r) * ld + col + q * 8);
        }
#pragma unroll
        for (int it = 0; it < 4; ++it) {           // B: 128 rows (gate*32+jl)
            const int idx = tid + it * 256;
            const int r = idx >> 3, q = idx & 7;
            const int gate = r >> 5, jl = r & 31;
            cp16(bbase + (uint32_t)(r * PITCH + q * 8) * 2,
                 W + (size_t)(gate * HH + j0 + jl) * ld + col + q * 8);
        }
        CP_COMMIT();
    };

    const int arow_off = lane & 15, acol_off = (lane >> 4) << 3;
    const int b_gsel = (lane >> 3) & 1;            // gate parity within pair
    const int b_kadd = (lane >> 4) << 3;
    const int b_jrow = wn * 8 + (lane & 7);

    auto compute = [&](int s) {
        const uint32_t abase = sbase + (uint32_t)(s * STG_ELEMS) * 2;
        const uint32_t bbase = abase + A_STG * 2;
#pragma unroll
        for (int kh = 0; kh < 4; ++kh) {
            const int kc = kh * 16;
            unsigned a[2][4], bA[4], bB[4];
            // bA: gates 0,1 ; bB: gates 2,3 (per-lane gathered rows)
            ldsm4(bA, bbase + (uint32_t)((b_gsel * 32 + b_jrow) * PITCH + kc + b_kadd) * 2);
            ldsm4(bB, bbase + (uint32_t)(((2 + b_gsel) * 32 + b_jrow) * PITCH + kc + b_kadd) * 2);
#pragma unroll
            for (int mi = 0; mi < 2; ++mi) {
                const int row = wm * 32 + mi * 16 + arow_off;
                ldsm4(a[mi], abase + (uint32_t)(row * PITCH + kc + acol_off) * 2);
            }
#pragma unroll
            for (int mi = 0; mi < 2; ++mi) {
                mma_bf16(acc[mi][0], a[mi], bA[0], bA[2]);
                mma_bf16(acc[mi][1], a[mi], bA[1], bA[3]);
                mma_bf16(acc[mi][2], a[mi], bB[0], bB[2]);
                mma_bf16(acc[mi][3], a[mi], bB[1], bB[3]);
            }
        }
    };

    load_stage(0, 0);
    load_stage(1, 1);
    load_stage(2, 2);

    for (int ci = 0; ci < NCH; ++ci) {
        const int rem = NCH - 1 - ci;
        if (rem >= 2)      { CP_WAIT(2); }
        else if (rem == 1) { CP_WAIT(1); }
        else               { CP_WAIT(0); }
        __syncthreads();
        if (ci + 3 < NCH) load_stage(ci + 3, (ci + 3) & 3);
        compute(ci & 3);
    }

    // ---------------- in-register epilogue ----------------
    const int g4 = lane >> 2, tg = lane & 3;
    const int j = j0 + wn * 8 + tg * 2;            // this thread's j-pair

    if (PRE) {
#pragma unroll
        for (int mi = 0; mi < 2; ++mi)
#pragma unroll
            for (int rh = 0; rh < 2; ++rh) {
                const int b = b0 + wm * 32 + mi * 16 + g4 + rh * 8;
                float* orow = gout + (size_t)b * (4 * HH) + j;
#pragma unroll
                for (int g = 0; g < 4; ++g) {
                    float2 v = make_float2(acc[mi][g][rh * 2], acc[mi][g][rh * 2 + 1]);
                    *reinterpret_cast<float2*>(orow + g * HH) = v;
                }
            }
    } else {
        float2 bsum[4];
#pragma unroll
        for (int g = 0; g < 4; ++g) {
            const float2 bi = *reinterpret_cast<const float2*>(bih + g * HH + j);
            const float2 bh = *reinterpret_cast<const float2*>(bhh + g * HH + j);
            bsum[g] = make_float2(bi.x + bh.x, bi.y + bh.y);
        }
#pragma unroll
        for (int mi = 0; mi < 2; ++mi)
#pragma unroll
            for (int rh = 0; rh < 2; ++rh) {
                const int b = b0 + wm * 32 + mi * 16 + g4 + rh * 8;
                float2 gv[4];
#pragma unroll
                for (int g = 0; g < 4; ++g)
                    gv[g] = make_float2(acc[mi][g][rh * 2] + bsum[g].x,
                                        acc[mi][g][rh * 2 + 1] + bsum[g].y);
                if (xpre) {
                    const float* xr = xpre + (size_t)b * (4 * HH) + j;
#pragma unroll
                    for (int g = 0; g < 4; ++g) {
                        const float2 xv = *reinterpret_cast<const float2*>(xr + g * HH);
                        gv[g].x += xv.x; gv[g].y += xv.y;
                    }
                }
                const size_t off = (size_t)b * HH + j;
                const float2 cv = *reinterpret_cast<const float2*>(c + off);

                const float i0 = sigm(gv[0].x), i1 = sigm(gv[0].y);
                const float f0 = sigm(gv[1].x), f1 = sigm(gv[1].y);
                const float g0 = tanhf(gv[2].x), g1 = tanhf(gv[2].y);
                const float o0 = sigm(gv[3].x), o1 = sigm(gv[3].y);
                const float cn0 = f0 * cv.x + i0 * g0;
                const float cn1 = f1 * cv.y + i1 * g1;
                *reinterpret_cast<float2*>(c + off) = make_float2(cn0, cn1);
                const float hn0 = o0 * tanhf(cn0);
                const float hn1 = o1 * tanhf(cn1);
                const bf16 h0 = __float2bfloat16(hn0);
                const bf16 h1 = __float2bfloat16(hn1);
                __nv_bfloat162 hi2 = __nv_bfloat162(h0, h1);
                __nv_bfloat162 lo2 = __nv_bfloat162(
                    __float2bfloat16(hn0 - __bfloat162float(h0)),
                    __float2bfloat16(hn1 - __bfloat162float(h1)));
                *reinterpret_cast<__nv_bfloat162*>(ho_hi + off) = hi2;
                *reinterpret_cast<__nv_bfloat162*>(ho_lo + off) = lo2;
            }
    }
}

// ---------------- prep / init / finalize ------------------------------------
__global__ void split_kernel(const float* __restrict__ src, bf16* __restrict__ hi,
                             bf16* __restrict__ lo, int n) {
    int i = blockIdx.x * blockDim.x + threadIdx.x;
    const int st = gridDim.x * blockDim.x;
    for (; i < n; i += st) {
        const float v = src[i];
        const bf16 h = __float2bfloat16(v);
        hi[i] = h;
        lo[i] = __float2bfloat16(v - __bfloat162float(h));
    }
}

__global__ void init_state_kernel() {
    int idx = blockIdx.x * blockDim.x + threadIdx.x;
    const int st = gridDim.x * blockDim.x;
    const int N1 = BB * H1, N3 = BB * H3;
    const bf16 z = __float2bfloat16(0.0f);
    for (int i = idx; i < N1; i += st) {
        g_h1_hi[0][i] = z; g_h1_lo[0][i] = z; g_h1_hi[1][i] = z; g_h1_lo[1][i] = z;
        g_h2_hi[0][i] = z; g_h2_lo[0][i] = z; g_h2_hi[1][i] = z; g_h2_lo[1][i] = z;
        g_c1[i] = 0.f; g_c2[i] = 0.f;
    }
    for (int i = idx; i < N3; i += st) {
        g_h3_hi[0][i] = z; g_h3_lo[0][i] = z; g_h3_hi[1][i] = z; g_h3_lo[1][i] = z;
        g_c3[i] = 0.f;
    }
}

// final h reconstructed as hi + lo (error ~1e-6, well under tolerance)
__global__ void finalize_kernel(float* __restrict__ out) {
    int idx = blockIdx.x * blockDim.x + threadIdx.x;
    const int st = gridDim.x * blockDim.x;
    const int N1 = BB * H1, N3 = BB * H3;
    for (int i = idx; i < N1; i += st) {
        out[0 * N1 + i] = __bfloat162float(g_h1_hi[0][i]) + __bfloat162float(g_h1_lo[0][i]);
        out[1 * N1 + i] = g_c1[i];
        out[2 * N1 + i] = __bfloat162float(g_h2_hi[0][i]) + __bfloat162float(g_h2_lo[0][i]);
        out[3 * N1 + i] = g_c2[i];
    }
    for (int i = idx; i < N3; i += st) {
        out[4 * N1 + i] = __bfloat162float(g_h3_hi[0][i]) + __bfloat162float(g_h3_lo[0][i]);
        out[4 * N1 + N3 + i] = g_c3[i];
    }
}

// ---------------- launch ----------------------------------------------------
extern "C" void kernel_launch(void* const* d_in, const int* in_sizes, int n_in,
                              void* d_out, int out_size) {
    const float* x    = (const float*)d_in[0];
    const float* Wih1 = (const float*)d_in[1];
    const float* Whh1 = (const float*)d_in[2];
    const float* bih1 = (const float*)d_in[3];
    const float* bhh1 = (const float*)d_in[4];
    const float* Wih2 = (const float*)d_in[5];
    const float* Whh2 = (const float*)d_in[6];
    const float* bih2 = (const float*)d_in[7];
    const float* bhh2 = (const float*)d_in[8];
    const float* Wih3 = (const float*)d_in[9];
    const float* Whh3 = (const float*)d_in[10];
    const float* bih3 = (const float*)d_in[11];
    const float* bhh3 = (const float*)d_in[12];
    float* out = (float*)d_out;

    bf16 *x_hi, *x_lo;
    bf16 *W1i_hi, *W1i_lo, *W1h_hi, *W1h_lo;
    bf16 *W2i_hi, *W2i_lo, *W2h_hi, *W2h_lo;
    bf16 *W3i_hi, *W3i_lo, *W3h_hi, *W3h_lo;
    bf16 *h1_hi, *h1_lo, *h2_hi, *h2_lo, *h3_hi, *h3_lo;
    float *c1, *c2, *c3, *xpre;

    cudaGetSymbolAddress((void**)&x_hi, g_x_hi);
    cudaGetSymbolAddress((void**)&x_lo, g_x_lo);
    cudaGetSymbolAddress((void**)&xpre, g_xpre);
    cudaGetSymbolAddress((void**)&W1i_hi, g_W1i_hi);
    cudaGetSymbolAddress((void**)&W1i_lo, g_W1i_lo);
    cudaGetSymbolAddress((void**)&W1h_hi, g_W1h_hi);
    cudaGetSymbolAddress((void**)&W1h_lo, g_W1h_lo);
    cudaGetSymbolAddress((void**)&W2i_hi, g_W2i_hi);
    cudaGetSymbolAddress((void**)&W2i_lo, g_W2i_lo);
    cudaGetSymbolAddress((void**)&W2h_hi, g_W2h_hi);
    cudaGetSymbolAddress((void**)&W2h_lo, g_W2h_lo);
    cudaGetSymbolAddress((void**)&W3i_hi, g_W3i_hi);
    cudaGetSymbolAddress((void**)&W3i_lo, g_W3i_lo);
    cudaGetSymbolAddress((void**)&W3h_hi, g_W3h_hi);
    cudaGetSymbolAddress((void**)&W3h_lo, g_W3h_lo);
    cudaGetSymbolAddress((void**)&h1_hi, g_h1_hi);
    cudaGetSymbolAddress((void**)&h1_lo, g_h1_lo);
    cudaGetSymbolAddress((void**)&h2_hi, g_h2_hi);
    cudaGetSymbolAddress((void**)&h2_lo, g_h2_lo);
    cudaGetSymbolAddress((void**)&h3_hi, g_h3_hi);
    cudaGetSymbolAddress((void**)&h3_lo, g_h3_lo);
    cudaGetSymbolAddress((void**)&c1, g_c1);
    cudaGetSymbolAddress((void**)&c2, g_c2);
    cudaGetSymbolAddress((void**)&c3, g_c3);

    cudaFuncSetAttribute(gemm_kernel<DIN, 0, H1, true>,
                         cudaFuncAttributeMaxDynamicSharedMemorySize, DYN_BYTES);
    cudaFuncSetAttribute(gemm_kernel<H1, 0, H1, false>,
                         cudaFuncAttributeMaxDynamicSharedMemorySize, DYN_BYTES);
    cudaFuncSetAttribute(gemm_kernel<H1, H2, H2, false>,
                         cudaFuncAttributeMaxDynamicSharedMemorySize, DYN_BYTES);
    cudaFuncSetAttribute(gemm_kernel<H2, H3, H3, false>,
                         cudaFuncAttributeMaxDynamicSharedMemorySize, DYN_BYTES);

    static cudaStream_t s1 = nullptr, s2 = nullptr, s3 = nullptr;
    static cudaEvent_t ev1r[4], ev2r[4], ev3r[4], evFork, evJ1, evJ2, evJ3;
    if (!s1) {
        cudaStreamCreateWithFlags(&s1, cudaStreamNonBlocking);
        cudaStreamCreateWithFlags(&s2, cudaStreamNonBlocking);
        cudaStreamCreateWithFlags(&s3, cudaStreamNonBlocking);
        for (int i = 0; i < 4; ++i) {
            cudaEventCreateWithFlags(&ev1r[i], cudaEventDisableTiming);
            cudaEventCreateWithFlags(&ev2r[i], cudaEventDisableTiming);
            cudaEventCreateWithFlags(&ev3r[i], cudaEventDisableTiming);
        }
        cudaEventCreateWithFlags(&evFork, cudaEventDisableTiming);
        cudaEventCreateWithFlags(&evJ1, cudaEventDisableTiming);
        cudaEventCreateWithFlags(&evJ2, cudaEventDisableTiming);
        cudaEventCreateWithFlags(&evJ3, cudaEventDisableTiming);
    }

    // -------- prologue (legacy stream) --------
    split_kernel<<<2048, 256>>>(x, x_hi, x_lo, TT * BB * DIN);
    split_kernel<<<1024, 256>>>(Wih1, W1i_hi, W1i_lo, 4 * H1 * DIN);
    split_kernel<<<1024, 256>>>(Whh1, W1h_hi, W1h_lo, 4 * H1 * H1);
    split_kernel<<<1024, 256>>>(Wih2, W2i_hi, W2i_lo, 4 * H2 * H1);
    split_kernel<<<1024, 256>>>(Whh2, W2h_hi, W2h_lo, 4 * H2 * H2);
    split_kernel<<<1024, 256>>>(Wih3, W3i_hi, W3i_lo, 4 * H3 * H2);
    split_kernel<<<1024, 256>>>(Whh3, W3h_hi, W3h_lo, 4 * H3 * H3);
    init_state_kernel<<<512, 256>>>();

    // big precompute: X1 = x @ Wih1^T for all T*B rows
    gemm_kernel<DIN, 0, H1, true><<<dim3(H1 / 32, TT * BB / BM), 256, DYN_BYTES>>>(
        x_hi, x_lo, nullptr, nullptr, W1i_hi, W1i_lo, nullptr, nullptr,
        nullptr, nullptr, nullptr, nullptr, nullptr, nullptr, xpre);

    cudaEventRecord(evFork, 0);
    cudaStreamWaitEvent(s1, evFork, 0);
    cudaStreamWaitEvent(s2, evFork, 0);
    cudaStreamWaitEvent(s3, evFork, 0);

    const int N1 = BB * H1, N2 = BB * H2, N3 = BB * H3;

    for (int t = 0; t < TT; ++t) {
        const int pi = t & 1, po = (t + 1) & 1;

        if (t >= 2) cudaStreamWaitEvent(s1, ev2r[(t - 2) & 3], 0);
        gemm_kernel<H1, 0, H1, false><<<dim3(H1 / 32, BB / BM), 256, DYN_BYTES, s1>>>(
            h1_hi + pi * N1, h1_lo + pi * N1, nullptr, nullptr,
            W1h_hi, W1h_lo, nullptr, nullptr,
            bih1, bhh1, xpre + (size_t)t * BB * 4 * H1,
            c1, h1_hi + po * N1, h1_lo + po * N1, nullptr);
        cudaEventRecord(ev1r[t & 3], s1);

        cudaStreamWaitEvent(s2, ev1r[t & 3], 0);
        if (t >= 2) cudaStreamWaitEvent(s2, ev3r[(t - 2) & 3], 0);
        gemm_kernel<H1, H2, H2, false><<<dim3(H2 / 32, BB / BM), 256, DYN_BYTES, s2>>>(
            h1_hi + po * N1, h1_lo + po * N1, h2_hi + pi * N2, h2_lo + pi * N2,
            W2i_hi, W2i_lo, W2h_hi, W2h_lo,
            bih2, bhh2, nullptr,
            c2, h2_hi + po * N2, h2_lo + po * N2, nullptr);
        cudaEventRecord(ev2r[t & 3], s2);

        cudaStreamWaitEvent(s3, ev2r[t & 3], 0);
        gemm_kernel<H2, H3, H3, false><<<dim3(H3 / 32, BB / BM), 256, DYN_BYTES, s3>>>(
            h2_hi + po * N2, h2_lo + po * N2, h3_hi + pi * N3, h3_lo + pi * N3,
            W3i_hi, W3i_lo, W3h_hi, W3h_lo,
            bih3, bhh3, nullptr,
            c3, h3_hi + po * N3, h3_lo + po * N3, nullptr);
        cudaEventRecord(ev3r[t & 3], s3);
    }

    cudaEventRecord(evJ1, s1);
    cudaEventRecord(evJ2, s2);
    cudaEventRecord(evJ3, s3);
    cudaStreamWaitEvent(0, evJ1, 0);
    cudaStreamWaitEvent(0, evJ2, 0);
    cudaStreamWaitEvent(0, evJ3, 0);

    finalize_kernel<<<256, 256>>>(out);
}